// round 4
// baseline (speedup 1.0000x reference)
#include <cuda_runtime.h>
#include <cstdint>

#define BB      8
#define CTOT    256
#define HH      96
#define WW      128
#define ROWT    HH                // one output row per block
#define CCK     4                 // channels per chunk
#define NCHUNK  (CTOT/CCK)        // 64
#define THREADS 288               // 9 warps (one per dy)

#define S2_ROWSTRIDE 576                       // bytes (144 floats; 136 used)
#define S2_CSTRIDE   (9*S2_ROWSTRIDE)          // 5184
#define S1_CSTRIDE   512                       // 128 floats, 1 row per channel
#define S1_BYTES     (CCK*S1_CSTRIDE)          // 2048
#define S2_BYTES     (CCK*S2_CSTRIDE)          // 20736
#define BUF_BYTES    (S1_BYTES + S2_BYTES)     // 22784
#define SMEM_TOTAL   (2*BUF_BYTES)             // 45568 -> 3 blocks/SM

typedef unsigned long long ull;

__device__ __forceinline__ float4 lds128(uint32_t addr) {
    float4 v;
    asm volatile("ld.shared.v4.f32 {%0,%1,%2,%3}, [%4];"
                 : "=f"(v.x), "=f"(v.y), "=f"(v.z), "=f"(v.w) : "r"(addr));
    return v;
}
__device__ __forceinline__ void sts_zero16(uint32_t addr) {
    asm volatile("st.shared.v4.b32 [%0], {%1,%1,%1,%1};" :: "r"(addr), "r"(0) : "memory");
}
__device__ __forceinline__ void cpa16(uint32_t dst, const float* src) {
    asm volatile("cp.async.cg.shared.global [%0], [%1], 16;" :: "r"(dst), "l"(src));
}
__device__ __forceinline__ ull pk(float lo, float hi) {
    ull r;
    asm("mov.b64 %0, {%1,%2};" : "=l"(r) : "f"(lo), "f"(hi));
    return r;
}
__device__ __forceinline__ float2 upk(ull v) {
    float2 f;
    asm("mov.b64 {%0,%1}, %2;" : "=f"(f.x), "=f"(f.y) : "l"(v));
    return f;
}
__device__ __forceinline__ void ffma2(ull& d, ull a, ull b) {
    asm("fma.rn.f32x2 %0, %1, %2, %0;" : "+l"(d) : "l"(a), "l"(b));
}

// Division-free loader: warp w owns in2 halo row rr=w for all CCK channels;
// lane = 16B chunk. Warps 0..CCK-1 also load the in1 row for channel c=warp.
__device__ __forceinline__ void load_chunk(uint32_t bufbase,
                                           const float* __restrict__ in1,
                                           const float* __restrict__ in2,
                                           int b, int c0, int h0,
                                           int warp, int lane, bool rowOK)
{
    const uint32_t s2b = bufbase + S1_BYTES;
    if (rowOK) {
        const int hh = h0 - 4 + warp;
        const float* src0 = in2 + ((((size_t)b * CTOT + c0) * HH + hh) * WW) + lane * 4;
        const uint32_t dst0 = s2b + (uint32_t)(warp * S2_ROWSTRIDE) + (uint32_t)((lane + 1) * 16);
#pragma unroll
        for (int c = 0; c < CCK; c++)
            cpa16(dst0 + c * S2_CSTRIDE, src0 + (size_t)c * HH * WW);
    }
    if (warp < CCK) {
        const float* src = in1 + ((((size_t)b * CTOT + c0 + warp) * HH + h0) * WW) + lane * 4;
        cpa16(bufbase + (uint32_t)(warp * S1_CSTRIDE) + (uint32_t)(lane * 16), src);
    }
    asm volatile("cp.async.commit_group;" ::: "memory");
}

__device__ __forceinline__ void compute_chunk(uint32_t bufbase,
                                              const uint32_t offA,
                                              const uint32_t* offB, ull acc[9][2])
{
#pragma unroll
    for (int cc = 0; cc < CCK; cc++) {
        float4 qa = lds128(bufbase + cc * S1_CSTRIDE + offA);
        const uint32_t s2b = bufbase + S1_BYTES + cc * S2_CSTRIDE;
        float4 q0 = lds128(s2b + offB[0]);
        float4 q1 = lds128(s2b + offB[1]);
        float4 q2 = lds128(s2b + offB[2]);

        ull A0 = pk(qa.x, qa.y);
        ull A1 = pk(qa.z, qa.w);

        float rv[12] = { q0.x, q0.y, q0.z, q0.w,
                         q1.x, q1.y, q1.z, q1.w,
                         q2.x, q2.y, q2.z, q2.w };
        ull E[6], O[5];
#pragma unroll
        for (int j = 0; j < 6; j++) E[j] = pk(rv[2 * j], rv[2 * j + 1]);
#pragma unroll
        for (int j = 0; j < 5; j++) O[j] = pk(rv[2 * j + 1], rv[2 * j + 2]);

#pragma unroll
        for (int d = 0; d < 9; d++) {
            ull b0 = (d & 1) ? O[(d >> 1)]     : E[(d >> 1)];
            ull b1 = (d & 1) ? O[(d >> 1) + 1] : E[(d >> 1) + 1];
            ffma2(acc[d][0], A0, b0);
            ffma2(acc[d][1], A1, b1);
        }
    }
}

__global__ void __launch_bounds__(THREADS, 3)
corr_kernel(const float* __restrict__ in1, const float* __restrict__ in2,
            float* __restrict__ out)
{
    extern __shared__ char smem[];
    const uint32_t smem32 = (uint32_t)__cvta_generic_to_shared(smem);

    const int tid  = threadIdx.x;
    const int warp = tid >> 5;        // dy index 0..8
    const int lane = tid & 31;
    const int w0   = lane << 2;

    const int bx = blockIdx.x;
    const int b  = bx / ROWT;
    const int h0 = bx - b * ROWT;     // output row

    const int hhal = h0 - 4 + warp;   // this warp's halo row
    const bool rowOK = (hhal >= 0) && (hhal < HH);

    const uint32_t offA = (uint32_t)(16 * lane);
    uint32_t offB[3];
#pragma unroll
    for (int j = 0; j < 3; j++)
        offB[j] = (uint32_t)(warp * S2_ROWSTRIDE + 16 * lane + 16 * j);

    // Pre-zero pad regions of both buffers (left/right halo chunks + OOB rows).
    // Warp-mapped: warp w zeroes its row rr=w in both buffers for all channels.
    if (lane < 2 * CCK) {
        int buf = lane >> 2;          // 0..1
        int c   = lane & 3;           // 0..CCK-1
        uint32_t rowaddr = smem32 + buf * BUF_BYTES + S1_BYTES
                         + c * S2_CSTRIDE + warp * S2_ROWSTRIDE;
        sts_zero16(rowaddr);                       // left pad (floats -4..-1)
        sts_zero16(rowaddr + 33u * 16u);           // right pad (floats 128..131)
        if (!rowOK) {
#pragma unroll
            for (int ch = 1; ch < 33; ch++) sts_zero16(rowaddr + (uint32_t)(ch * 16));
        }
    }

    ull acc[9][2];
#pragma unroll
    for (int d = 0; d < 9; d++) { acc[d][0] = 0ull; acc[d][1] = 0ull; }

    load_chunk(smem32, in1, in2, b, 0, h0, warp, lane, rowOK);

    for (int k = 0; k < NCHUNK; k++) {
        if (k + 1 < NCHUNK) {
            load_chunk(smem32 + (uint32_t)(((k + 1) & 1) * BUF_BYTES), in1, in2,
                       b, (k + 1) * CCK, h0, warp, lane, rowOK);
            asm volatile("cp.async.wait_group 1;" ::: "memory");
        } else {
            asm volatile("cp.async.wait_group 0;" ::: "memory");
        }
        __syncthreads();
        compute_chunk(smem32 + (uint32_t)((k & 1) * BUF_BYTES), offA, offB, acc);
        __syncthreads();
    }

    // Epilogue: out[b, warp*9+d, h0, w0..w0+3] = acc / 256
    const float inv = 1.0f / 256.0f;
#pragma unroll
    for (int d = 0; d < 9; d++) {
        int n = warp * 9 + d;
        float* op = out + ((size_t)((b * 81 + n) * HH + h0)) * WW + w0;
        float2 u0 = upk(acc[d][0]);
        float2 u1 = upk(acc[d][1]);
        *(float4*)op = make_float4(u0.x * inv, u0.y * inv, u1.x * inv, u1.y * inv);
    }
}

extern "C" void kernel_launch(void* const* d_in, const int* in_sizes, int n_in,
                              void* d_out, int out_size)
{
    const float* in1 = (const float*)d_in[0];
    const float* in2 = (const float*)d_in[1];
    float* out = (float*)d_out;

    cudaFuncSetAttribute(corr_kernel, cudaFuncAttributeMaxDynamicSharedMemorySize, SMEM_TOTAL);
    corr_kernel<<<BB * ROWT, THREADS, SMEM_TOTAL>>>(in1, in2, out);
}